// round 10
// baseline (speedup 1.0000x reference)
#include <cuda_runtime.h>
#include <cuda_bf16.h>
#include <cstdint>

// Problem constants
#define B_MOLS 256
#define M_ATOMS 48
#define EDGES_PER_MOL (M_ATOMS * (M_ATOMS - 1))   // 2256
#define E_TOTAL (B_MOLS * EDGES_PER_MOL)          // 577536
#define N_ATOMS (B_MOLS * M_ATOMS)                // 12288
#define K_RBF 32
#define HS 128
#define NSH 25
#define FEAT_W 57                                  // 32 RBF + 25 SH

// Output layout (flattened reference tuple, float32)
#define OFF_FEAT 0ULL
#define OFF_EMB  ((size_t)E_TOTAL * FEAT_W)                    // 32919552
#define OFF_EI   (OFF_EMB + (size_t)N_ATOMS * HS)              // 34492416
#define OFF_TR   (OFF_EI + 2ULL * E_TOTAL)                     // 35647488

#define TPB 256
#define EPB 128                                                 // edges per block
#define EDGE_BLOCKS (E_TOTAL / EPB)                            // 4512
#define EMB_F4 (N_ATOMS * HS / 4)                              // 393216
#define EMB_BLOCKS (EMB_F4 / TPB)                              // 1536

#define LOG2E 1.4426950408889634f

// log2 C(31, v), v = 0..31
__constant__ float c_lb2[K_RBF] = {
    0.0f,       4.954196f,  8.861087f, 12.134094f,
    14.941449f, 17.374408f, 19.489885f, 21.326386f,
    22.911349f, 24.264986f, 25.402490f, 26.335418f,
    27.072384f, 27.620101f, 27.982671f, 28.163244f,
    28.163244f, 27.982671f, 27.620101f, 27.072384f,
    26.335418f, 25.402490f, 24.264986f, 22.911349f,
    21.326386f, 19.489885f, 17.374408f, 14.941449f,
    12.134094f, 8.861087f,  4.954196f,  0.0f
};

// sqrt((2l+1)(l-|m|)!/(l+|m|)!) * (sqrt(2) if m!=0), j = l*l+l+m
__constant__ float c_shcoef[NSH] = {
    1.0f,
    1.7320508f, 1.7320508f, 1.7320508f,
    0.6454972f, 1.2909944f, 2.2360680f, 1.2909944f, 0.6454972f,
    0.1394333f, 0.3415650f, 1.0801234f, 2.6457513f, 1.0801234f, 0.3415650f, 0.1394333f,
    0.0211289f, 0.0597614f, 0.2236068f, 0.9486833f, 3.0f,
    0.9486833f, 0.2236068f, 0.0597614f, 0.0211289f
};

__device__ __forceinline__ uint32_t smem_addr(const void* p) {
    uint32_t a;
    asm("{ .reg .u64 t; cvta.to.shared.u64 t, %1; cvt.u32.u64 %0, t; }" : "=r"(a) : "l"(p));
    return a;
}

__device__ __forceinline__ float ex2f(float x) {
    float y;
    asm("ex2.approx.ftz.f32 %0, %1;" : "=f"(y) : "f"(x));
    return y;
}

// ---------------------------------------------------------------------------
// Fused kernel, 256 threads / 128 edges per edge-block (2 threads per edge):
//   tid 0..127   -> SH (25 comps) + edge/transpose indices   (sqrt/rcp only)
//   tid 128..255 -> all 32 RBF components                    (MUFU-heavy)
// Warp pair (w, w+4) covers rows [w*32, w*32+32); they sync on named barrier
// (w+1, 64 threads), then warp w's lane 0 bulk-stores the 7296B slice.
// smem/thread = 114B -> 7 CTAs x 256 thr = 1792 threads/SM.
// ---------------------------------------------------------------------------
__global__ __launch_bounds__(TPB) void fused_kernel(
    const float* __restrict__ pos,
    const float* __restrict__ alpha,
    const int*   __restrict__ an,
    const float* __restrict__ table,
    float* __restrict__ out)
{
    // ---------------- embedding-gather blocks ----------------
    if (blockIdx.x >= EDGE_BLOCKS) {
        const int i = (blockIdx.x - EDGE_BLOCKS) * TPB + threadIdx.x; // < EMB_F4
        const int n = i >> 5;            // 32 float4 per node (HS=128)
        const int h = i & 31;
        const int a = __ldg(&an[n]);
        const float4 v = ((const float4*)table)[a * 32 + h];
        ((float4*)(out + OFF_EMB))[i] = v;
        return;
    }

    // ---------------- edge blocks ----------------
    __shared__ __align__(16) float sfeat[EPB * FEAT_W];   // 29184 B

    const int half = threadIdx.x >> 7;        // 0: SH+idx, 1: RBF
    const int t7   = threadIdx.x & 127;       // edge slot in block
    const int e0 = blockIdx.x * EPB;
    const int e  = e0 + t7;

    // Decode edge -> (b, src s, dst d)
    const int b = e / EDGES_PER_MOL;
    const int t = e - b * EDGES_PER_MOL;
    const int s = t / (M_ATOMS - 1);
    const int k = t - s * (M_ATOMS - 1);
    const int d = k + (k >= s ? 1 : 0);
    const int dst = b * M_ATOMS + d;
    const int src = b * M_ATOMS + s;

    // Edge vector (pos: 147 KB, L1/L2-resident)
    const float ex = pos[dst * 3 + 0] - pos[src * 3 + 0];
    const float ey = pos[dst * 3 + 1] - pos[src * 3 + 1];
    const float ez = pos[dst * 3 + 2] - pos[src * 3 + 2];
    float r = sqrtf(ex * ex + ey * ey + ez * ez);
    r = fmaxf(r, 1e-6f);

    float* row = &sfeat[t7 * FEAT_W];

    if (half) {
        // ---- RBF in log2 space: row[v] = 2^(lb2[v] + base + v*w2) ----
        const float a  = 0.5f * alpha[0];
        const float xx = -a * r;
        const float lp = __logf(-expm1f(xx));        // ln(1 - e^{xx})
        const float rc  = r * (1.0f / 15.0f);
        const float den = fmaxf((1.0f - rc) * (1.0f + rc), 1e-9f);
        const float lnfcut = (rc < 1.0f) ? (-rc * rc * __frcp_rn(den)) : -1.0e9f;
        const float base = (31.0f * xx + lnfcut) * LOG2E;
        const float w2   = (lp - xx) * LOG2E;
        #pragma unroll
        for (int v = 0; v < K_RBF; v++) {
            row[v] = ex2f(fmaf((float)v, w2, base + c_lb2[v]));
        }
    } else {
        // ---- SH (component-normalized, z-up), LMAX=4 ----
        const float inv_r = 1.0f / r;
        const float x = ex * inv_r, y = ey * inv_r, z = ez * inv_r;

        const float C1 = x,               S1 = y;
        const float C2 = C1 * x - S1 * y, S2 = S1 * x + C1 * y;
        const float C3 = C2 * x - S2 * y, S3 = S2 * x + C2 * y;
        const float C4 = C3 * x - S3 * y, S4 = S3 * x + C3 * y;

        const float Q00 = 1.0f;
        const float Q10 = z;
        const float Q20 = (3.0f * z * Q10 - 1.0f * Q00) * 0.5f;
        const float Q30 = (5.0f * z * Q20 - 2.0f * Q10) * (1.0f / 3.0f);
        const float Q40 = (7.0f * z * Q30 - 3.0f * Q20) * 0.25f;
        const float Q11 = 1.0f;
        const float Q21 = 3.0f * z;
        const float Q31 = (5.0f * z * Q21 - 3.0f * Q11) * 0.5f;
        const float Q41 = (7.0f * z * Q31 - 4.0f * Q21) * (1.0f / 3.0f);
        const float Q22 = 3.0f;
        const float Q32 = 5.0f * z * Q22;
        const float Q42 = (7.0f * z * Q32 - 5.0f * Q22) * 0.5f;
        const float Q33 = 15.0f;
        const float Q43 = 7.0f * z * Q33;
        const float Q44 = 105.0f;

        float* sh = row + K_RBF;
        sh[0]  = c_shcoef[0];
        sh[1]  = c_shcoef[1]  * Q11 * S1;
        sh[2]  = c_shcoef[2]  * Q10;
        sh[3]  = c_shcoef[3]  * Q11 * C1;
        sh[4]  = c_shcoef[4]  * Q22 * S2;
        sh[5]  = c_shcoef[5]  * Q21 * S1;
        sh[6]  = c_shcoef[6]  * Q20;
        sh[7]  = c_shcoef[7]  * Q21 * C1;
        sh[8]  = c_shcoef[8]  * Q22 * C2;
        sh[9]  = c_shcoef[9]  * Q33 * S3;
        sh[10] = c_shcoef[10] * Q32 * S2;
        sh[11] = c_shcoef[11] * Q31 * S1;
        sh[12] = c_shcoef[12] * Q30;
        sh[13] = c_shcoef[13] * Q31 * C1;
        sh[14] = c_shcoef[14] * Q32 * C2;
        sh[15] = c_shcoef[15] * Q33 * C3;
        sh[16] = c_shcoef[16] * Q44 * S4;
        sh[17] = c_shcoef[17] * Q43 * S3;
        sh[18] = c_shcoef[18] * Q42 * S2;
        sh[19] = c_shcoef[19] * Q41 * S1;
        sh[20] = c_shcoef[20] * Q40;
        sh[21] = c_shcoef[21] * Q41 * C1;
        sh[22] = c_shcoef[22] * Q42 * C2;
        sh[23] = c_shcoef[23] * Q43 * C3;
        sh[24] = c_shcoef[24] * Q44 * C4;

        // ---- edge_index + transpose_index (coalesced scalar stores) ----
        out[OFF_EI + e]           = (float)dst;
        out[OFF_EI + E_TOTAL + e] = (float)src;
        const int tr = b * EDGES_PER_MOL + d * (M_ATOMS - 1) + s - (d < s ? 1 : 0);
        out[OFF_TR + e] = (float)tr;
    }

    // ---- pair-wise sync (warp w with warp w+4), then per-slice TMA drain ----
    const int w = t7 >> 5;                    // slice index 0..3
    asm volatile("bar.sync %0, 64;" :: "r"(w + 1) : "memory");

    if (half == 0 && (t7 & 31) == 0) {
        asm volatile("fence.proxy.async.shared::cta;" ::: "memory");
        const uint32_t src_s = smem_addr(&sfeat[w * 32 * FEAT_W]);   // 7296B slice
        void* dst_g = (void*)(out + (size_t)(e0 + w * 32) * FEAT_W); // 16B aligned
        asm volatile(
            "cp.async.bulk.global.shared::cta.bulk_group [%0], [%1], %2;"
            :: "l"(dst_g), "r"(src_s), "n"(32 * FEAT_W * 4) : "memory");
        asm volatile("cp.async.bulk.commit_group;" ::: "memory");
        asm volatile("cp.async.bulk.wait_group.read 0;" ::: "memory");
    }
}

extern "C" void kernel_launch(void* const* d_in, const int* in_sizes, int n_in,
                              void* d_out, int out_size) {
    const float* pos   = (const float*)d_in[0];
    const int*   an    = (const int*)d_in[1];
    const float* table = (const float*)d_in[2];
    const float* alpha = (const float*)d_in[3];
    float* out = (float*)d_out;

    fused_kernel<<<EDGE_BLOCKS + EMB_BLOCKS, TPB>>>(pos, alpha, an, table, out);
}